// round 12
// baseline (speedup 1.0000x reference)
#include <cuda_runtime.h>
#include <cuda_bf16.h>

// Problem constants (fixed shapes)
constexpr int QN = 16;      // query rows
constexpr int D  = 384;     // embedding dim
constexpr int NV = D / 4;   // float4 per row
constexpr int N  = 50000;   // corpus docs
constexpr int TOTAL = QN * N;
constexpr int BINBITS = 13;              // sign+8exp+4mant
constexpr int NBIN = 1 << BINBITS;       // 8192 buckets per row

// GEMM tiling
constexpr int TILE = 128;            // docs per block (1 per thread)
constexpr int KC   = 32;             // k-chunk (floats)
constexpr int NCH  = D / KC;         // 12 chunks
constexpr int CP4  = 9;              // c-row pitch in float4 (36 floats, padded)
constexpr int NTB  = (N + TILE - 1) / TILE;   // 391 blocks

constexpr int PBT = 1024;            // threads in pav_bucket block
constexpr int BPT = NBIN / PBT;      // 8 bins per thread
constexpr int NMRG = 32;             // level-1 mergers
constexpr int LPM  = PBT / NMRG;     // 32 thread-lists per merger
constexpr int MCAP = LPM * BPT;      // 256 bucket cap per merger list

constexpr float FXS_F = 4398046511104.0f;  // 2^42 (pow2 -> exact fp32 scale)
constexpr double FXS = 4398046511104.0;

// ---------------- static device scratch (no allocations allowed) ------------
__device__ float              g_qn[QN * D];       // normalized queries
__device__ float              g_simt[TOTAL];      // transposed sims [doc][16]
__device__ unsigned           g_cnt[QN * NBIN];   // bucket counts
__device__ unsigned long long g_zsum[QN * NBIN];  // bucket sum(z), fixed-point
__device__ double             g_bmean[QN * NBIN]; // bucket -> its block mean

__device__ double g_asum[QN * PBT * BPT];  // phase-A per-thread lists
__device__ int    g_acnt[QN * PBT * BPT];
__device__ int    g_anb[QN * PBT];

__device__ double g_m1s[QN * NMRG * MCAP]; // level-1 merged lists
__device__ int    g_m1c[QN * NMRG * MCAP];
__device__ int    g_m1n[QN * NMRG];

__device__ double g_fs[QN * NBIN];         // final block means
__device__ int    g_fc[QN * NBIN];
__device__ int    g_fe[QN * NBIN];         // final block ends
__device__ int    g_B[QN];                 // final block counts

__device__ __forceinline__ unsigned ord_of(unsigned u) {
    return u ^ ((u & 0x80000000u) ? 0xFFFFFFFFu : 0x80000000u);
}

// ---------------- q normalize (once) -----------------------------------------
__global__ __launch_bounds__(512) void qnorm_kernel(const float* __restrict__ qg)
{
    const int w = threadIdx.x >> 5, lane = threadIdx.x & 31;  // warp = row
    const float4* src = reinterpret_cast<const float4*>(qg) + w * NV;
    float4 v[3];
    float ss = 0.f;
    #pragma unroll
    for (int j = 0; j < 3; j++) {
        v[j] = src[lane + 32 * j];
        ss += v[j].x*v[j].x + v[j].y*v[j].y + v[j].z*v[j].z + v[j].w*v[j].w;
    }
    #pragma unroll
    for (int o = 16; o; o >>= 1)
        ss += __shfl_xor_sync(0xFFFFFFFFu, ss, o);
    float s = 1.0f / fmaxf(sqrtf(ss), 1e-12f);
    float4* dst = reinterpret_cast<float4*>(g_qn) + w * NV;
    #pragma unroll
    for (int j = 0; j < 3; j++) {
        float4 o4 = v[j];
        o4.x *= s; o4.y *= s; o4.z *= s; o4.w *= s;
        dst[lane + 32 * j] = o4;
    }
}

// ---------------- sims GEMM: thread-per-doc, smem-tiled, no shuffles ---------
__global__ __launch_bounds__(TILE) void sim_tile_kernel(
    const float* __restrict__ cg, float* __restrict__ simt,
    unsigned* __restrict__ cnt, unsigned long long* __restrict__ zsum)
{
    __shared__ float4 qsh[QN * NV];        // 24 KB normalized q, [r][k/4]
    __shared__ float4 sc[TILE * CP4];      // 18 KB c chunk, [doc][9]
    const int tid = threadIdx.x;
    const int d0 = blockIdx.x * TILE;
    const int doc = d0 + tid;
    const bool valid = doc < N;

    {
        const float4* qn4 = reinterpret_cast<const float4*>(g_qn);
        #pragma unroll
        for (int i = 0; i < (QN * NV) / TILE; i++)
            qsh[tid + i * TILE] = qn4[tid + i * TILE];
    }
    __syncthreads();

    const float4* cg4 = reinterpret_cast<const float4*>(cg);
    float acc[QN];
    #pragma unroll
    for (int r = 0; r < QN; r++) acc[r] = 0.f;
    float ss = 0.f;

    for (int ch = 0; ch < NCH; ch++) {
        const int k4 = ch * (KC / 4);
        // stage 128 docs x 32 floats (8 f4/doc); 8 consecutive lanes = one doc row
        #pragma unroll
        for (int i = 0; i < 8; i++) {
            int idx = tid + i * TILE;
            int dd = idx >> 3, f4 = idx & 7;
            int gdoc = min(d0 + dd, N - 1);
            sc[dd * CP4 + f4] = cg4[(size_t)gdoc * NV + k4 + f4];
        }
        __syncthreads();

        #pragma unroll
        for (int f4 = 0; f4 < 8; f4++) {
            float4 cv = sc[tid * CP4 + f4];
            ss += cv.x*cv.x + cv.y*cv.y + cv.z*cv.z + cv.w*cv.w;
            #pragma unroll
            for (int r = 0; r < QN; r++) {
                float4 qv = qsh[r * NV + k4 + f4];   // warp-uniform broadcast
                acc[r] += qv.x*cv.x + qv.y*cv.y + qv.z*cv.z + qv.w*cv.w;
            }
        }
        __syncthreads();
    }

    if (valid) {
        float cinv = 1.0f / fmaxf(sqrtf(ss), 1e-12f);
        float4* st4 = reinterpret_cast<float4*>(simt) + doc * (QN / 4);
        #pragma unroll
        for (int j = 0; j < QN / 4; j++) {
            float4 o4;
            o4.x = acc[j*4+0] * cinv; o4.y = acc[j*4+1] * cinv;
            o4.z = acc[j*4+2] * cinv; o4.w = acc[j*4+3] * cinv;
            st4[j] = o4;
        }
        #pragma unroll
        for (int r = 0; r < QN; r++) {
            float sim = acc[r] * cinv;
            unsigned u = __float_as_uint(sim);
            unsigned bin = ((unsigned)r << BINBITS) | (ord_of(u) >> (32 - BINBITS));
            atomicAdd(&cnt[bin], 1u);
            float z = sim * -10.0f;
            long long q = __float2ll_rn(z * FXS_F);   // exact pow2 scale
            atomicAdd(&zsum[bin], (unsigned long long)q);
        }
    }
}

// ---------------- fused bucket PAV + bucket->mean map ------------------------
// One block per row, 1024 threads, 8 contiguous bins each. Bucket at start
// position p with count c pools into (sum = Sz - c*N + c*p + c*(c-1)/2, c).
__global__ __launch_bounds__(PBT) void pav_bucket_kernel(
    const unsigned* __restrict__ cnt, const unsigned long long* __restrict__ zsum,
    double* __restrict__ bmean)
{
    const int row = blockIdx.x;
    const int t = threadIdx.x;
    const int b0 = row * NBIN + t * BPT;

    unsigned lcnt[BPT];
    {
        const uint4* p4 = reinterpret_cast<const uint4*>(cnt + b0);
        #pragma unroll
        for (int j = 0; j < BPT / 4; j++) {
            uint4 v = p4[j];
            lcnt[j*4+0] = v.x; lcnt[j*4+1] = v.y;
            lcnt[j*4+2] = v.z; lcnt[j*4+3] = v.w;
        }
    }
    unsigned tsum = 0;
    #pragma unroll
    for (int j = 0; j < BPT; j++) tsum += lcnt[j];

    __shared__ unsigned s[PBT];
    s[t] = tsum;
    __syncthreads();
    #pragma unroll
    for (int off = 1; off < PBT; off <<= 1) {
        unsigned v = (t >= off) ? s[t - off] : 0u;
        __syncthreads();
        s[t] += v;
        __syncthreads();
    }
    unsigned texcl = s[t] - tsum;

    unsigned lpre[BPT];
    double ls[BPT];
    int    lc[BPT];
    int nb = 0;
    {
        unsigned p = texcl;
        #pragma unroll
        for (int j = 0; j < BPT; j++) {
            lpre[j] = p;
            unsigned c = lcnt[j];
            if (c) {
                double zs = (double)(long long)zsum[b0 + j] * (1.0 / FXS);
                double dc = (double)c;
                double cs = zs - dc * (double)N + dc * (double)p
                            + 0.5 * dc * (double)(c - 1);
                int cc = (int)c;
                while (nb > 0 && ls[nb - 1] * (double)cc < cs * (double)lc[nb - 1]) {
                    cs += ls[nb - 1]; cc += lc[nb - 1]; nb--;
                }
                ls[nb] = cs; lc[nb] = cc; nb++;
            }
            p += c;
        }
    }
    const int ob = (row * PBT + t) * BPT;
    #pragma unroll
    for (int b = 0; b < BPT; b++) {
        if (b < nb) { g_asum[ob + b] = ls[b]; g_acnt[ob + b] = lc[b]; }
    }
    g_anb[row * PBT + t] = nb;
    __syncthreads();

    if (t < NMRG) {
        const int mb = (row * NMRG + t) * MCAP;
        int B = 0;
        for (int tt = t * LPM; tt < t * LPM + LPM; tt++) {
            int nbt = g_anb[row * PBT + tt];
            const int bb = (row * PBT + tt) * BPT;
            for (int b = 0; b < nbt; b++) {
                double cs = g_asum[bb + b];
                int cc = g_acnt[bb + b];
                while (B > 0 && g_m1s[mb + B - 1] * (double)cc < cs * (double)g_m1c[mb + B - 1]) {
                    cs += g_m1s[mb + B - 1]; cc += g_m1c[mb + B - 1]; B--;
                }
                g_m1s[mb + B] = cs; g_m1c[mb + B] = cc; B++;
            }
        }
        g_m1n[row * NMRG + t] = B;
    }
    __syncthreads();

    if (t == 0) {
        const int fb = row * NBIN;
        int B = 0;
        for (int m = 0; m < NMRG; m++) {
            int nm = g_m1n[row * NMRG + m];
            const int mb = (row * NMRG + m) * MCAP;
            for (int b = 0; b < nm; b++) {
                double cs = g_m1s[mb + b];
                int cc = g_m1c[mb + b];
                while (B > 0 && g_fs[fb + B - 1] * (double)cc < cs * (double)g_fc[fb + B - 1]) {
                    cs += g_fs[fb + B - 1]; cc += g_fc[fb + B - 1]; B--;
                }
                g_fs[fb + B] = cs; g_fc[fb + B] = cc; B++;
            }
        }
        int e = 0;
        for (int b = 0; b < B; b++) {
            e += g_fc[fb + b];
            g_fe[fb + b] = e;
            g_fs[fb + b] = g_fs[fb + b] / (double)g_fc[fb + b];  // -> mean
        }
        g_B[row] = B;
    }
    __syncthreads();

    // Bucket -> block-mean map (one search per nonempty bucket)
    {
        const int fb = row * NBIN;
        const int B = g_B[row];
        #pragma unroll
        for (int j = 0; j < BPT; j++) {
            if (lcnt[j]) {
                int p = (int)lpre[j];
                int loB = 0, hiB = B;
                while (loB < hiB) {
                    int mid = (loB + hiB) >> 1;
                    if (g_fe[fb + mid] > p) hiB = mid; else loB = mid + 1;
                }
                bmean[b0 + j] = g_fs[fb + loB];
            }
        }
    }
}

// ---------------- transpose + rank: fully coalesced in and out ---------------
__global__ __launch_bounds__(256) void rankT_kernel(
    const float* __restrict__ simt, const double* __restrict__ bmean,
    float* __restrict__ sims, float* __restrict__ ranks)
{
    __shared__ float st[QN][257];
    const int t = threadIdx.x;
    const int doc = blockIdx.x * 256 + t;

    if (doc < N) {
        const uint4* p4 = reinterpret_cast<const uint4*>(simt + (size_t)doc * QN);
        #pragma unroll
        for (int j = 0; j < 4; j++) {
            uint4 v = p4[j];
            st[j*4+0][t] = __uint_as_float(v.x);
            st[j*4+1][t] = __uint_as_float(v.y);
            st[j*4+2][t] = __uint_as_float(v.z);
            st[j*4+3][t] = __uint_as_float(v.w);
        }
    }
    __syncthreads();

    if (doc >= N) return;
    #pragma unroll
    for (int r = 0; r < QN; r++) {
        float sim = st[r][t];
        unsigned u = __float_as_uint(sim);
        unsigned bin = ((unsigned)r << BINBITS) | (ord_of(u) >> (32 - BINBITS));
        double mean = bmean[bin];
        float z = sim * -10.0f;
        int gi = r * N + doc;
        sims[gi] = sim;
        ranks[gi] = (float)((double)z - mean);
    }
}

// ---------------- launch -----------------------------------------------------
extern "C" void kernel_launch(void* const* d_in, const int* in_sizes, int n_in,
                              void* d_out, int out_size)
{
    const float* q = (const float*)d_in[0];
    const float* c = (const float*)d_in[1];
    float* out = (float*)d_out;
    float* sims = out;            // [QN*N]
    float* ranks = out + TOTAL;   // [QN*N]

    void *pc = nullptr, *pz = nullptr, *pm = nullptr, *pst = nullptr;
    cudaGetSymbolAddress(&pc, g_cnt);
    cudaGetSymbolAddress(&pz, g_zsum);
    cudaGetSymbolAddress(&pm, g_bmean);
    cudaGetSymbolAddress(&pst, g_simt);

    cudaMemsetAsync(pc, 0, QN * NBIN * sizeof(unsigned));
    cudaMemsetAsync(pz, 0, QN * NBIN * sizeof(unsigned long long));

    qnorm_kernel<<<1, 512>>>(q);
    sim_tile_kernel<<<NTB, TILE>>>(c, (float*)pst, (unsigned*)pc,
                                   (unsigned long long*)pz);
    pav_bucket_kernel<<<QN, PBT>>>((const unsigned*)pc,
                                   (const unsigned long long*)pz,
                                   (double*)pm);
    rankT_kernel<<<(N + 255) / 256, 256>>>((const float*)pst,
                                           (const double*)pm, sims, ranks);
}

// round 13
// speedup vs baseline: 1.8328x; 1.8328x over previous
#include <cuda_runtime.h>
#include <cuda_bf16.h>

// Problem constants (fixed shapes)
constexpr int QN = 16;      // query rows
constexpr int D  = 384;     // embedding dim
constexpr int NV = D / 4;   // float4 per row
constexpr int N  = 50000;   // corpus docs
constexpr int TOTAL = QN * N;
constexpr int BINBITS = 13;              // sign+8exp+4mant
constexpr int NBIN = 1 << BINBITS;       // 8192 buckets per row

// GEMM tiling
constexpr int TILE = 128;            // docs per block (1 per thread)
constexpr int KC   = 32;             // k-chunk (floats)
constexpr int NCH  = D / KC;         // 12 chunks
constexpr int NTB  = (N + TILE - 1) / TILE;   // 391 blocks

constexpr int PBT = 1024;            // threads in pav_bucket block
constexpr int BPT = NBIN / PBT;      // 8 bins per thread
constexpr int NMRG = 32;             // level-1 mergers
constexpr int LPM  = PBT / NMRG;     // 32 thread-lists per merger
constexpr int MCAP = LPM * BPT;      // 256 bucket cap per merger list

constexpr int RDOC = 128;            // docs per rankT block

constexpr float FXS_F = 4398046511104.0f;  // 2^42 (pow2 -> exact fp32 scale)
constexpr double FXS = 4398046511104.0;

// ---------------- static device scratch (no allocations allowed) ------------
__device__ float              g_qn[QN * D];       // normalized queries
__device__ float              g_simt[TOTAL];      // transposed sims [doc][16]
__device__ unsigned           g_cnt[QN * NBIN];   // bucket counts
__device__ unsigned long long g_zsum[QN * NBIN];  // bucket sum(z), fixed-point
__device__ float              g_bmeanf[QN * NBIN];// bucket -> its block mean

__device__ double g_asum[QN * PBT * BPT];  // phase-A per-thread lists
__device__ int    g_acnt[QN * PBT * BPT];
__device__ int    g_anb[QN * PBT];

__device__ double g_m1s[QN * NMRG * MCAP]; // level-1 merged lists
__device__ int    g_m1c[QN * NMRG * MCAP];
__device__ int    g_m1n[QN * NMRG];

__device__ double g_fs[QN * NBIN];         // final block means
__device__ int    g_fc[QN * NBIN];
__device__ int    g_fe[QN * NBIN];         // final block ends
__device__ int    g_B[QN];                 // final block counts

__device__ __forceinline__ unsigned ord_of(unsigned u) {
    return u ^ ((u & 0x80000000u) ? 0xFFFFFFFFu : 0x80000000u);
}

__device__ __forceinline__ void cp16(void* dst_smem, const void* src) {
    unsigned s = (unsigned)__cvta_generic_to_shared(dst_smem);
    asm volatile("cp.async.cg.shared.global [%0], [%1], 16;" :: "r"(s), "l"(src));
}

// ---------------- q normalize (once) -----------------------------------------
__global__ __launch_bounds__(512) void qnorm_kernel(const float* __restrict__ qg)
{
    const int w = threadIdx.x >> 5, lane = threadIdx.x & 31;  // warp = row
    const float4* src = reinterpret_cast<const float4*>(qg) + w * NV;
    float4 v[3];
    float ss = 0.f;
    #pragma unroll
    for (int j = 0; j < 3; j++) {
        v[j] = src[lane + 32 * j];
        ss += v[j].x*v[j].x + v[j].y*v[j].y + v[j].z*v[j].z + v[j].w*v[j].w;
    }
    #pragma unroll
    for (int o = 16; o; o >>= 1)
        ss += __shfl_xor_sync(0xFFFFFFFFu, ss, o);
    float s = 1.0f / fmaxf(sqrtf(ss), 1e-12f);
    float4* dst = reinterpret_cast<float4*>(g_qn) + w * NV;
    #pragma unroll
    for (int j = 0; j < 3; j++) {
        float4 o4 = v[j];
        o4.x *= s; o4.y *= s; o4.z *= s; o4.w *= s;
        dst[lane + 32 * j] = o4;
    }
}

// ---------------- sims GEMM: thread-per-doc, cp.async double-buffered --------
__global__ __launch_bounds__(TILE) void sim_tile_kernel(
    const float* __restrict__ cg, float* __restrict__ simt,
    unsigned* __restrict__ cnt, unsigned long long* __restrict__ zsum)
{
    __shared__ float4 qsh[QN * NV];        // 24 KB normalized q, [r][k/4]
    __shared__ float4 sc[2][TILE * 8];     // 2 x 16 KB c chunks, XOR-swizzled
    const int tid = threadIdx.x;
    const int d0 = blockIdx.x * TILE;
    const int doc = d0 + tid;
    const bool valid = doc < N;
    const float4* cg4 = reinterpret_cast<const float4*>(cg);

    // stage chunk `ch` into buffer `buf` (async)
    auto stage = [&](int ch, int buf) {
        const int k4 = ch * (KC / 4);
        #pragma unroll
        for (int i = 0; i < 8; i++) {
            int idx = tid + i * TILE;
            int dd = idx >> 3, f4 = idx & 7;
            int gdoc = min(d0 + dd, N - 1);
            cp16(&sc[buf][dd * 8 + (f4 ^ (dd & 7))],
                 &cg4[(size_t)gdoc * NV + k4 + f4]);
        }
        asm volatile("cp.async.commit_group;" ::: "memory");
    };

    stage(0, 0);
    stage(1, 1);

    {   // stage q while c chunks are in flight
        const float4* qn4 = reinterpret_cast<const float4*>(g_qn);
        #pragma unroll
        for (int i = 0; i < (QN * NV) / TILE; i++)
            qsh[tid + i * TILE] = qn4[tid + i * TILE];
    }

    float acc[QN];
    #pragma unroll
    for (int r = 0; r < QN; r++) acc[r] = 0.f;
    float ss = 0.f;

    const int sw = (tid & 7);   // xor swizzle key for this thread's row
    for (int ch = 0; ch < NCH; ch++) {
        if (ch < NCH - 1) asm volatile("cp.async.wait_group 1;" ::: "memory");
        else              asm volatile("cp.async.wait_group 0;" ::: "memory");
        __syncthreads();

        const float4* crow = &sc[ch & 1][tid * 8];
        const int k4 = ch * (KC / 4);
        #pragma unroll
        for (int f4 = 0; f4 < 8; f4++) {
            float4 cv = crow[f4 ^ sw];
            ss += cv.x*cv.x + cv.y*cv.y + cv.z*cv.z + cv.w*cv.w;
            #pragma unroll
            for (int r = 0; r < QN; r++) {
                float4 qv = qsh[r * NV + k4 + f4];   // warp-uniform broadcast
                acc[r] += qv.x*cv.x + qv.y*cv.y + qv.z*cv.z + qv.w*cv.w;
            }
        }
        __syncthreads();
        if (ch + 2 < NCH) stage(ch + 2, ch & 1);
    }

    if (valid) {
        float cinv = 1.0f / fmaxf(sqrtf(ss), 1e-12f);
        float4* st4 = reinterpret_cast<float4*>(simt) + doc * (QN / 4);
        #pragma unroll
        for (int j = 0; j < QN / 4; j++) {
            float4 o4;
            o4.x = acc[j*4+0] * cinv; o4.y = acc[j*4+1] * cinv;
            o4.z = acc[j*4+2] * cinv; o4.w = acc[j*4+3] * cinv;
            st4[j] = o4;
        }
        #pragma unroll
        for (int r = 0; r < QN; r++) {
            float sim = acc[r] * cinv;
            unsigned u = __float_as_uint(sim);
            unsigned bin = ((unsigned)r << BINBITS) | (ord_of(u) >> (32 - BINBITS));
            atomicAdd(&cnt[bin], 1u);
            float z = sim * -10.0f;
            long long q = __float2ll_rn(z * FXS_F);   // exact pow2 scale
            atomicAdd(&zsum[bin], (unsigned long long)q);
        }
    }
}

// ---------------- fused bucket PAV + bucket->mean map ------------------------
// One block per row, 1024 threads, 8 contiguous bins each. Bucket at start
// position p with count c pools into (sum = Sz - c*N + c*p + c*(c-1)/2, c).
__global__ __launch_bounds__(PBT) void pav_bucket_kernel(
    const unsigned* __restrict__ cnt, const unsigned long long* __restrict__ zsum,
    float* __restrict__ bmean)
{
    const int row = blockIdx.x;
    const int t = threadIdx.x;
    const int b0 = row * NBIN + t * BPT;

    unsigned lcnt[BPT];
    {
        const uint4* p4 = reinterpret_cast<const uint4*>(cnt + b0);
        #pragma unroll
        for (int j = 0; j < BPT / 4; j++) {
            uint4 v = p4[j];
            lcnt[j*4+0] = v.x; lcnt[j*4+1] = v.y;
            lcnt[j*4+2] = v.z; lcnt[j*4+3] = v.w;
        }
    }
    unsigned tsum = 0;
    #pragma unroll
    for (int j = 0; j < BPT; j++) tsum += lcnt[j];

    __shared__ unsigned s[PBT];
    s[t] = tsum;
    __syncthreads();
    #pragma unroll
    for (int off = 1; off < PBT; off <<= 1) {
        unsigned v = (t >= off) ? s[t - off] : 0u;
        __syncthreads();
        s[t] += v;
        __syncthreads();
    }
    unsigned texcl = s[t] - tsum;

    unsigned lpre[BPT];
    double ls[BPT];
    int    lc[BPT];
    int nb = 0;
    {
        unsigned p = texcl;
        #pragma unroll
        for (int j = 0; j < BPT; j++) {
            lpre[j] = p;
            unsigned c = lcnt[j];
            if (c) {
                double zs = (double)(long long)zsum[b0 + j] * (1.0 / FXS);
                double dc = (double)c;
                double cs = zs - dc * (double)N + dc * (double)p
                            + 0.5 * dc * (double)(c - 1);
                int cc = (int)c;
                while (nb > 0 && ls[nb - 1] * (double)cc < cs * (double)lc[nb - 1]) {
                    cs += ls[nb - 1]; cc += lc[nb - 1]; nb--;
                }
                ls[nb] = cs; lc[nb] = cc; nb++;
            }
            p += c;
        }
    }
    const int ob = (row * PBT + t) * BPT;
    #pragma unroll
    for (int b = 0; b < BPT; b++) {
        if (b < nb) { g_asum[ob + b] = ls[b]; g_acnt[ob + b] = lc[b]; }
    }
    g_anb[row * PBT + t] = nb;
    __syncthreads();

    if (t < NMRG) {
        const int mb = (row * NMRG + t) * MCAP;
        int B = 0;
        for (int tt = t * LPM; tt < t * LPM + LPM; tt++) {
            int nbt = g_anb[row * PBT + tt];
            const int bb = (row * PBT + tt) * BPT;
            for (int b = 0; b < nbt; b++) {
                double cs = g_asum[bb + b];
                int cc = g_acnt[bb + b];
                while (B > 0 && g_m1s[mb + B - 1] * (double)cc < cs * (double)g_m1c[mb + B - 1]) {
                    cs += g_m1s[mb + B - 1]; cc += g_m1c[mb + B - 1]; B--;
                }
                g_m1s[mb + B] = cs; g_m1c[mb + B] = cc; B++;
            }
        }
        g_m1n[row * NMRG + t] = B;
    }
    __syncthreads();

    if (t == 0) {
        const int fb = row * NBIN;
        int B = 0;
        for (int m = 0; m < NMRG; m++) {
            int nm = g_m1n[row * NMRG + m];
            const int mb = (row * NMRG + m) * MCAP;
            for (int b = 0; b < nm; b++) {
                double cs = g_m1s[mb + b];
                int cc = g_m1c[mb + b];
                while (B > 0 && g_fs[fb + B - 1] * (double)cc < cs * (double)g_fc[fb + B - 1]) {
                    cs += g_fs[fb + B - 1]; cc += g_fc[fb + B - 1]; B--;
                }
                g_fs[fb + B] = cs; g_fc[fb + B] = cc; B++;
            }
        }
        int e = 0;
        for (int b = 0; b < B; b++) {
            e += g_fc[fb + b];
            g_fe[fb + b] = e;
            g_fs[fb + b] = g_fs[fb + b] / (double)g_fc[fb + b];  // -> mean
        }
        g_B[row] = B;
    }
    __syncthreads();

    // Bucket -> block-mean map (one search per nonempty bucket)
    {
        const int fb = row * NBIN;
        const int B = g_B[row];
        #pragma unroll
        for (int j = 0; j < BPT; j++) {
            if (lcnt[j]) {
                int p = (int)lpre[j];
                int loB = 0, hiB = B;
                while (loB < hiB) {
                    int mid = (loB + hiB) >> 1;
                    if (g_fe[fb + mid] > p) hiB = mid; else loB = mid + 1;
                }
                bmean[b0 + j] = (float)g_fs[fb + loB];
            }
        }
    }
}

// ---------------- transpose + rank: 128 docs/block, half-warp row split ------
__global__ __launch_bounds__(256) void rankT_kernel(
    const float* __restrict__ simt, const float* __restrict__ bmean,
    float* __restrict__ sims, float* __restrict__ ranks)
{
    __shared__ float st[QN][RDOC + 1];
    const int t = threadIdx.x;
    const int d0 = blockIdx.x * RDOC;

    // load 128 docs x 16 sims (512 uint4), 2 per thread
    #pragma unroll
    for (int j = 0; j < 2; j++) {
        int idx = t + j * 256;
        int dl = idx >> 2, q4 = idx & 3;
        int doc = d0 + dl;
        if (doc < N) {
            uint4 v = reinterpret_cast<const uint4*>(simt + (size_t)doc * QN)[q4];
            st[q4*4+0][dl] = __uint_as_float(v.x);
            st[q4*4+1][dl] = __uint_as_float(v.y);
            st[q4*4+2][dl] = __uint_as_float(v.z);
            st[q4*4+3][dl] = __uint_as_float(v.w);
        }
    }
    __syncthreads();

    const int dl = t & (RDOC - 1);
    const int half = t >> 7;              // 0: rows 0-7, 1: rows 8-15
    const int doc = d0 + dl;
    if (doc >= N) return;

    #pragma unroll
    for (int rr = 0; rr < QN / 2; rr++) {
        int r = half * (QN / 2) + rr;
        float sim = st[r][dl];
        unsigned u = __float_as_uint(sim);
        unsigned bin = ((unsigned)r << BINBITS) | (ord_of(u) >> (32 - BINBITS));
        float mean = bmean[bin];
        float z = sim * -10.0f;
        int gi = r * N + doc;
        sims[gi] = sim;
        ranks[gi] = (float)((double)z - (double)mean);
    }
}

// ---------------- launch -----------------------------------------------------
extern "C" void kernel_launch(void* const* d_in, const int* in_sizes, int n_in,
                              void* d_out, int out_size)
{
    const float* q = (const float*)d_in[0];
    const float* c = (const float*)d_in[1];
    float* out = (float*)d_out;
    float* sims = out;            // [QN*N]
    float* ranks = out + TOTAL;   // [QN*N]

    void *pc = nullptr, *pz = nullptr, *pm = nullptr, *pst = nullptr;
    cudaGetSymbolAddress(&pc, g_cnt);
    cudaGetSymbolAddress(&pz, g_zsum);
    cudaGetSymbolAddress(&pm, g_bmeanf);
    cudaGetSymbolAddress(&pst, g_simt);

    cudaMemsetAsync(pc, 0, QN * NBIN * sizeof(unsigned));
    cudaMemsetAsync(pz, 0, QN * NBIN * sizeof(unsigned long long));

    qnorm_kernel<<<1, 512>>>(q);
    sim_tile_kernel<<<NTB, TILE>>>(c, (float*)pst, (unsigned*)pc,
                                   (unsigned long long*)pz);
    pav_bucket_kernel<<<QN, PBT>>>((const unsigned*)pc,
                                   (const unsigned long long*)pz,
                                   (float*)pm);
    rankT_kernel<<<(N + RDOC - 1) / RDOC, 256>>>((const float*)pst,
                                                 (const float*)pm, sims, ranks);
}